// round 7
// baseline (speedup 1.0000x reference)
#include <cuda_runtime.h>
#include <cuda_fp16.h>

#define NN      131072
#define KK      27
#define C       32
#define DCAP    64                 // dense bucket width (Poisson(27), P(cnt>64) ~ 1e-9 total)
#define SENT    (NN << 5)          // sentinel entry: zero data row, k=0
#define BN_BLKS 1024
#define EPS_F   1e-5f
#define NPC     16                 // nodes per CTA in fused kernel
#define SSTR    868                // S stride per node in floats (864 + 4 pad)
#define FUSED_SMEM (NPC * SSTR * 4)   // 55552 B

// -------- device scratch --------
__device__ int    g_fill[NN];
__device__ __align__(16) int g_dense[(size_t)NN * DCAP];  // 33.5 MB padded buckets
__device__ __align__(128) __half2 g_data16[(NN + 1) * 16]; // 8 MB fp16 data + zero row
__device__ __align__(8)  unsigned g_btf[27 * 4 * 4 * 32 * 2]; // 110 KB: W as tf32 B-frags
__device__ float  g_part[BN_BLKS * 64];
__device__ float  g_stats[64];

__device__ __forceinline__ unsigned f2tf32(float f) {
    unsigned r;
    asm("cvt.rna.tf32.f32 %0, %1;" : "=r"(r) : "f"(f));
    return r;
}

// -------- 1a. sentinel-fill dense table, zero counters, zero data row --------
__global__ __launch_bounds__(256) void k_sent() {
    int i = blockIdx.x * blockDim.x + threadIdx.x;       // < 1048576
    int4 s4 = make_int4(SENT, SENT, SENT, SENT);
#pragma unroll
    for (int u = 0; u < 2; ++u)
        reinterpret_cast<int4*>(g_dense)[i * 2 + u] = s4;
    if (i < NN) g_fill[i] = 0;
    if (i < 8)  reinterpret_cast<uint2*>(g_data16 + NN * 16)[i] = make_uint2(0u, 0u);
}

// -------- 1b. init: data->fp16, W->tf32 B-frags --------
// btf[((kb*4+s)*4+t)*32+l][r] = tf32( weight[kb][ s*8+(l&3)+r*4 ][ t*8+(l>>2) ] )
__global__ void k_init(const float* __restrict__ data,
                       const float* __restrict__ weight) {
    int i = blockIdx.x * blockDim.x + threadIdx.x;       // < 524288
#pragma unroll
    for (int u = 0; u < 2; ++u) {
        int idx = i * 2 + u;
        float4 v = reinterpret_cast<const float4*>(data)[idx];
        __half2 h0 = __floats2half2_rn(v.x, v.y);
        __half2 h1 = __floats2half2_rn(v.z, v.w);
        uint2 s;
        s.x = *reinterpret_cast<unsigned*>(&h0);
        s.y = *reinterpret_cast<unsigned*>(&h1);
        reinterpret_cast<uint2*>(g_data16)[idx] = s;
    }
    if (i < 27 * 1024) {
        int r = i & 1, l = (i >> 1) & 31, t = (i >> 6) & 3, s = (i >> 8) & 3, kb = i >> 10;
        int krow = s * 8 + (l & 3) + r * 4;
        int ncol = t * 8 + (l >> 2);
        g_btf[i] = f2tf32(weight[(kb * 32 + krow) * 32 + ncol]);
    }
}

// -------- 2. build dense inverse index, bucketed by output node m --------
__global__ __launch_bounds__(256) void k_fill(const int* __restrict__ neigh) {
    __shared__ int sn[256 * KK];
    int base = blockIdx.x * 256;
    for (int i = threadIdx.x; i < 256 * KK; i += 256)
        sn[i] = neigh[(size_t)base * KK + i];
    __syncthreads();
    int n = base + threadIdx.x;
#pragma unroll
    for (int j = 0; j < KK; ++j) {
        int m   = sn[threadIdx.x * KK + j];
        int pos = atomicAdd(&g_fill[m], 1);
        if (pos < DCAP) g_dense[(size_t)m * DCAP + pos] = (n << 5) | j;
    }
}

// -------- 3. fused gather + tf32 GEMM (512 thr, 16 nodes/CTA, 1 node/warp) --
// phase A: warp w gathers node w via dense 8-wide batches (8 independent data
// loads per step, sentinel entries add 0 from the L1-hot zero row).
// phase B: out[16x32] = S[16x864] @ Wcat[864x32] via mma.m16n8k8.tf32.
__global__ __launch_bounds__(512) void k_fused(float* __restrict__ out) {
    extern __shared__ float S[];
    const int tid = threadIdx.x, lane = tid & 31, w = tid >> 5;

    for (int i = tid; i < NPC * SSTR; i += 512) S[i] = 0.f;
    __syncthreads();

    // ---- phase A ----
    const int c2   = lane >> 1;
    const int hsel = lane & 1;
    const int node_g = blockIdx.x * NPC + w;
    float* Sn = S + w * SSTR;
    int cnt = g_fill[node_g];
    if (cnt > DCAP) cnt = DCAP;
    const int rounded = (cnt + 7) & ~7;
    const int* dl = g_dense + (size_t)node_g * DCAP;

    for (int j = 0; j < rounded; j += 8) {
        int4 ea = __ldcs(reinterpret_cast<const int4*>(dl + j));
        int4 eb = __ldcs(reinterpret_cast<const int4*>(dl + j + 4));
        __half2 h0 = g_data16[(ea.x >> 5) * 16 + c2];   // 8 independent loads
        __half2 h1 = g_data16[(ea.y >> 5) * 16 + c2];
        __half2 h2 = g_data16[(ea.z >> 5) * 16 + c2];
        __half2 h3 = g_data16[(ea.w >> 5) * 16 + c2];
        __half2 h4 = g_data16[(eb.x >> 5) * 16 + c2];
        __half2 h5 = g_data16[(eb.y >> 5) * 16 + c2];
        __half2 h6 = g_data16[(eb.z >> 5) * 16 + c2];
        __half2 h7 = g_data16[(eb.w >> 5) * 16 + c2];
        float v0 = hsel ? __high2float(h0) : __low2float(h0);
        float v1 = hsel ? __high2float(h1) : __low2float(h1);
        float v2 = hsel ? __high2float(h2) : __low2float(h2);
        float v3 = hsel ? __high2float(h3) : __low2float(h3);
        float v4 = hsel ? __high2float(h4) : __low2float(h4);
        float v5 = hsel ? __high2float(h5) : __low2float(h5);
        float v6 = hsel ? __high2float(h6) : __low2float(h6);
        float v7 = hsel ? __high2float(h7) : __low2float(h7);
        Sn[(ea.x & 31) * 32 + lane] += v0;
        Sn[(ea.y & 31) * 32 + lane] += v1;
        Sn[(ea.z & 31) * 32 + lane] += v2;
        Sn[(ea.w & 31) * 32 + lane] += v3;
        Sn[(eb.x & 31) * 32 + lane] += v4;
        Sn[(eb.y & 31) * 32 + lane] += v5;
        Sn[(eb.z & 31) * 32 + lane] += v6;
        Sn[(eb.w & 31) * 32 + lane] += v7;
    }
    __syncthreads();

    // ---- phase B (verified mapping, R5) ----
    float d[4][4];
#pragma unroll
    for (int t = 0; t < 4; ++t)
#pragma unroll
        for (int q = 0; q < 4; ++q) d[t][q] = 0.f;

    const int r0 = lane >> 2, cA = lane & 3;
#pragma unroll
    for (int pass = 0; pass < 2; ++pass) {
        int kb = w + pass * 16;
        if (kb >= KK) break;
#pragma unroll
        for (int s = 0; s < 4; ++s) {
            const float* Ab = S + kb * 32 + s * 8 + cA;
            unsigned a0 = f2tf32(Ab[(r0    ) * SSTR    ]);
            unsigned a1 = f2tf32(Ab[(r0 + 8) * SSTR    ]);
            unsigned a2 = f2tf32(Ab[(r0    ) * SSTR + 4]);
            unsigned a3 = f2tf32(Ab[(r0 + 8) * SSTR + 4]);
            const uint2* bp = reinterpret_cast<const uint2*>(g_btf) +
                              ((kb * 4 + s) * 4) * 32 + lane;
#pragma unroll
            for (int t = 0; t < 4; ++t) {
                uint2 b = bp[t * 32];
                asm volatile(
                    "mma.sync.aligned.m16n8k8.row.col.f32.tf32.tf32.f32 "
                    "{%0,%1,%2,%3}, {%4,%5,%6,%7}, {%8,%9}, {%0,%1,%2,%3};"
                    : "+f"(d[t][0]), "+f"(d[t][1]), "+f"(d[t][2]), "+f"(d[t][3])
                    : "r"(a0), "r"(a1), "r"(a2), "r"(a3), "r"(b.x), "r"(b.y));
            }
        }
    }
    __syncthreads();                      // all S reads done; reuse S for partials

    float* P = S + w * 512;
#pragma unroll
    for (int t = 0; t < 4; ++t) {
        *reinterpret_cast<float2*>(&P[(r0    ) * 32 + t * 8 + cA * 2]) =
            make_float2(d[t][0], d[t][1]);
        *reinterpret_cast<float2*>(&P[(r0 + 8) * 32 + t * 8 + cA * 2]) =
            make_float2(d[t][2], d[t][3]);
    }
    __syncthreads();

    float acc = 0.f;
#pragma unroll
    for (int ww = 0; ww < 16; ++ww) acc += S[ww * 512 + tid];
    out[(size_t)blockIdx.x * 512 + tid] = acc;
}

// -------- 4. BN stats, stage 1 --------
__global__ __launch_bounds__(256) void k_bnpart(const float* __restrict__ out) {
    __shared__ float ss[8][32], sq[8][32];
    int ch = threadIdx.x & 31, w = threadIdx.x >> 5;
    int r0 = blockIdx.x * (NN / BN_BLKS);
    float s = 0.f, q = 0.f;
    for (int r = r0 + w; r < r0 + (NN / BN_BLKS); r += 8) {
        float v = out[(size_t)r * C + ch];
        s += v;
        q += v * v;
    }
    ss[w][ch] = s;
    sq[w][ch] = q;
    __syncthreads();
    if (w == 0) {
        float S = 0.f, Q = 0.f;
#pragma unroll
        for (int t = 0; t < 8; ++t) { S += ss[t][ch]; Q += sq[t][ch]; }
        g_part[blockIdx.x * 64 + ch]      = S;
        g_part[blockIdx.x * 64 + 32 + ch] = Q;
    }
}

// -------- 5. BN stats, stage 2 --------
__global__ __launch_bounds__(256) void k_bnfinal(const float* __restrict__ gamma,
                                                 const float* __restrict__ beta) {
    __shared__ float ss[8][32], sq[8][32];
    int ch = threadIdx.x & 31, w = threadIdx.x >> 5;
    float S = 0.f, Q = 0.f;
    for (int b = w; b < BN_BLKS; b += 8) {
        S += g_part[b * 64 + ch];
        Q += g_part[b * 64 + 32 + ch];
    }
    ss[w][ch] = S;
    sq[w][ch] = Q;
    __syncthreads();
    if (w == 0) {
        float St = 0.f, Qt = 0.f;
#pragma unroll
        for (int t = 0; t < 8; ++t) { St += ss[t][ch]; Qt += sq[t][ch]; }
        float mean  = St * (1.0f / NN);
        float var   = Qt * (1.0f / NN) - mean * mean;
        float rstd  = rsqrtf(var + EPS_F);
        float scale = gamma[ch] * rstd;
        g_stats[ch]      = scale;
        g_stats[32 + ch] = beta[ch] - mean * scale;
    }
}

// -------- 6. apply BN + ReLU --------
__global__ __launch_bounds__(256) void k_apply(float* __restrict__ out) {
    int i = blockIdx.x * blockDim.x + threadIdx.x;
    if (i >= NN * C) return;
    int   ch = i & 31;
    float y  = fmaf(out[i], g_stats[ch], g_stats[32 + ch]);
    out[i] = fmaxf(y, 0.f);
}

extern "C" void kernel_launch(void* const* d_in, const int* in_sizes, int n_in,
                              void* d_out, int out_size) {
    const float* data   = (const float*)d_in[0];
    const float* weight = (const float*)d_in[1];
    const float* gamma  = (const float*)d_in[2];
    const float* beta   = (const float*)d_in[3];
    const int*   neigh  = (const int*)d_in[4];
    float*       out    = (float*)d_out;

    cudaFuncSetAttribute(k_fused, cudaFuncAttributeMaxDynamicSharedMemorySize,
                         FUSED_SMEM);

    k_sent<<<4096, 256>>>();
    k_init<<<2048, 256>>>(data, weight);
    k_fill<<<NN / 256, 256>>>(neigh);
    k_fused<<<NN / NPC, 512, FUSED_SMEM>>>(out);
    k_bnpart<<<BN_BLKS, 256>>>(out);
    k_bnfinal<<<1, 256>>>(gamma, beta);
    k_apply<<<(NN * C + 255) / 256, 256>>>(out);
}

// round 8
// speedup vs baseline: 1.6152x; 1.6152x over previous
#include <cuda_runtime.h>
#include <cuda_fp16.h>

#define NN      131072
#define KK      27
#define C       32
#define NCOL    (KK * C)           // 864 contrib columns
#define NKTOT   (NN * KK)          // 3538944 scatter entries; row NKTOT = zero sentinel
#define DCAP    64                 // dense bucket width (Poisson(27), P(cnt>64) ~ 1e-9)
#define EPS_F   1e-5f
#define GEMM_BLKS 1024             // NN/128
#define FILL_BLKS (NKTOT / 4 / 256)
#define GB      8192               // gather blocks = BN partial count

// -------- device scratch --------
__device__ __align__(16) __half g_contrib16[(size_t)NKTOT * C + C];  // 226 MB + sentinel row
__device__ int    g_fill[NN];
__device__ __align__(16) int g_dense[(size_t)NN * DCAP];             // 33.5 MB buckets
__device__ float  g_part[GB * 64];
__device__ float  g_part2[64 * 64];
__device__ float  g_stats[64];
__device__ __align__(16) unsigned g_bfrag[108 * 2 * 32 * 2];         // 55 KB: B frag order

__device__ __forceinline__ unsigned smem_u32(const void* p) {
    unsigned a;
    asm("{ .reg .u64 t; cvta.to.shared.u64 t, %1; cvt.u32.u64 %0, t; }" : "=r"(a) : "l"(p));
    return a;
}

// -------- 1. init: zero fill counters, zero sentinel row, B->mma frags ------
// Bfrag[nt][s][lane][reg]: k0 = s*16 + (l&3)*2 + reg*8, n = nt*8 + (l>>2),
// value half2( B[k0][n], B[k0+1][n] ), B[i][j] = weight[j/32][i][j%32].
__global__ void k_init(const float* __restrict__ weight) {
    int i = blockIdx.x * blockDim.x + threadIdx.x;
    if (i < NN) g_fill[i] = 0;
    if (i < 4) reinterpret_cast<uint4*>(g_contrib16 + (size_t)NKTOT * C)[i] =
        make_uint4(0u, 0u, 0u, 0u);
    if (i < 108 * 2 * 32 * 2) {
        int reg = i & 1, l = (i >> 1) & 31, s = (i >> 6) & 1, nt = i >> 7;
        int k0 = s * 16 + (l & 3) * 2 + reg * 8;
        int n  = nt * 8 + (l >> 2);
        int jk = n >> 5, o = n & 31;
        float lo = weight[(jk * 32 + k0) * 32 + o];
        float hi = weight[(jk * 32 + k0 + 1) * 32 + o];
        __half2 h = __floats2half2_rn(lo, hi);
        g_bfrag[i] = *reinterpret_cast<unsigned*>(&h);
    }
}

// -------- 2. merged work kernel: GEMM (blocks 0..1023) + fill (rest) --------
// (verbatim from the 182.7us R4 kernel; column perm p = j*8 + t*2 + b <-> o = t*8+j*2+b)
__global__ __launch_bounds__(256) void k_work(const float* __restrict__ data,
                                              const int* __restrict__ neigh) {
    __shared__ __align__(16) __half Ah[128][40];
    const int tid = threadIdx.x, lane = tid & 31, warp = tid >> 5;

    if (blockIdx.x >= GEMM_BLKS) {
        // ---- fill: build dense inverse index ----
        int t = (blockIdx.x - GEMM_BLKS) * 256 + tid;
        int4 m4 = __ldcs(reinterpret_cast<const int4*>(neigh) + t);
        int e0 = t * 4;
#pragma unroll
        for (int q = 0; q < 4; ++q) {
            int m   = (q == 0) ? m4.x : (q == 1) ? m4.y : (q == 2) ? m4.z : m4.w;
            int pos = atomicAdd(&g_fill[m], 1);
            if (pos < DCAP) __stcs(&g_dense[(size_t)m * DCAP + pos], e0 + q);
        }
        return;
    }

    // ---- GEMM ----
    const int bid = blockIdx.x;
    const float4* src = reinterpret_cast<const float4*>(data + (size_t)bid * 128 * C);
#pragma unroll
    for (int t0 = 0; t0 < 4; ++t0) {
        int    t = tid + t0 * 256;
        float4 v = src[t];
        int r = t >> 3, c = (t & 7) * 4;
        *reinterpret_cast<__half2*>(&Ah[r][c])     = __floats2half2_rn(v.x, v.y);
        *reinterpret_cast<__half2*>(&Ah[r][c + 2]) = __floats2half2_rn(v.z, v.w);
    }
    __syncthreads();

    unsigned a0[4], a1[4];
    {
        unsigned base = smem_u32(&Ah[warp * 16 + (lane & 15)][(lane >> 4) * 8]);
        asm volatile("ldmatrix.sync.aligned.m8n8.x4.shared.b16 {%0,%1,%2,%3}, [%4];"
                     : "=r"(a0[0]), "=r"(a0[1]), "=r"(a0[2]), "=r"(a0[3]) : "r"(base));
        asm volatile("ldmatrix.sync.aligned.m8n8.x4.shared.b16 {%0,%1,%2,%3}, [%4];"
                     : "=r"(a1[0]), "=r"(a1[1]), "=r"(a1[2]), "=r"(a1[3]) : "r"(base + 32));
    }

    const int r0 = lane >> 2;
    const int j  = lane & 3;
    const size_t nlo = (size_t)bid * 128 + warp * 16 + r0;
    __half* plo = g_contrib16 + nlo * NCOL + j * 8;
    __half* phi = plo + (size_t)8 * NCOL;

    const uint2* bf = reinterpret_cast<const uint2*>(g_bfrag) + lane;

    for (int kb = 0; kb < 27; ++kb) {
        uint2 b[8];
#pragma unroll
        for (int q = 0; q < 8; ++q) b[q] = bf[(kb * 8 + q) * 32];

        unsigned hlo[4], hhi[4];
#pragma unroll
        for (int t = 0; t < 4; ++t) {
            float d0 = 0.f, d1 = 0.f, d2 = 0.f, d3 = 0.f;
            asm volatile(
                "mma.sync.aligned.m16n8k16.row.col.f32.f16.f16.f32 "
                "{%0,%1,%2,%3}, {%4,%5,%6,%7}, {%8,%9}, {%0,%1,%2,%3};"
                : "+f"(d0), "+f"(d1), "+f"(d2), "+f"(d3)
                : "r"(a0[0]), "r"(a0[1]), "r"(a0[2]), "r"(a0[3]),
                  "r"(b[t * 2].x), "r"(b[t * 2].y));
            asm volatile(
                "mma.sync.aligned.m16n8k16.row.col.f32.f16.f16.f32 "
                "{%0,%1,%2,%3}, {%4,%5,%6,%7}, {%8,%9}, {%0,%1,%2,%3};"
                : "+f"(d0), "+f"(d1), "+f"(d2), "+f"(d3)
                : "r"(a1[0]), "r"(a1[1]), "r"(a1[2]), "r"(a1[3]),
                  "r"(b[t * 2 + 1].x), "r"(b[t * 2 + 1].y));
            __half2 l2 = __floats2half2_rn(d0, d1);
            __half2 h2 = __floats2half2_rn(d2, d3);
            hlo[t] = *reinterpret_cast<unsigned*>(&l2);
            hhi[t] = *reinterpret_cast<unsigned*>(&h2);
        }
        uint4 vlo = make_uint4(hlo[0], hlo[1], hlo[2], hlo[3]);
        uint4 vhi = make_uint4(hhi[0], hhi[1], hhi[2], hhi[3]);
        __stcs(reinterpret_cast<uint4*>(plo + kb * 32), vlo);
        __stcs(reinterpret_cast<uint4*>(phi + kb * 32), vhi);
    }
}

// -------- 3. gather + BN stage-1: warp = node, 8-lane group per entry ------
// lane: g = lane>>3 selects entry-of-4, c = lane&7 reads 8B (4 channels).
// Body = 8 entries: 2 bcast int4 list loads + 8 independent 64B-row loads
// (predicated to the zero sentinel row past cnt). Register accumulate,
// shfl-tree reduce, permuted channel write, per-CTA deterministic BN partials.
__global__ __launch_bounds__(512) void k_gather(float* __restrict__ out) {
    __shared__ float sm[16][33];
    const int tid = threadIdx.x, lane = tid & 31, w = tid >> 5;
    const int m = blockIdx.x * 16 + w;
    const int g = lane >> 3, c = lane & 7;

    int cnt = g_fill[m];
    if (cnt > DCAP) cnt = DCAP;
    const int* dl = g_dense + (size_t)m * DCAP;

    float4 acc = make_float4(0.f, 0.f, 0.f, 0.f);
    for (int j = 0; j < cnt; j += 8) {
        int4 ea = *reinterpret_cast<const int4*>(dl + j);
        int4 eb = *reinterpret_cast<const int4*>(dl + j + 4);
        int e1 = (g == 0) ? ea.x : (g == 1) ? ea.y : (g == 2) ? ea.z : ea.w;
        int e2 = (g == 0) ? eb.x : (g == 1) ? eb.y : (g == 2) ? eb.z : eb.w;
        e1 = (j + g     < cnt) ? e1 : NKTOT;      // sentinel -> zero row
        e2 = (j + 4 + g < cnt) ? e2 : NKTOT;
        uint2 d1 = __ldcs(reinterpret_cast<const uint2*>(
                       g_contrib16 + (size_t)e1 * C) + c);
        uint2 d2 = __ldcs(reinterpret_cast<const uint2*>(
                       g_contrib16 + (size_t)e2 * C) + c);
        float2 f;
        f = __half22float2(*reinterpret_cast<__half2*>(&d1.x)); acc.x += f.x; acc.y += f.y;
        f = __half22float2(*reinterpret_cast<__half2*>(&d1.y)); acc.z += f.x; acc.w += f.y;
        f = __half22float2(*reinterpret_cast<__half2*>(&d2.x)); acc.x += f.x; acc.y += f.y;
        f = __half22float2(*reinterpret_cast<__half2*>(&d2.y)); acc.z += f.x; acc.w += f.y;
    }
    // reduce 4 groups -> lanes 0-7
    acc.x += __shfl_down_sync(0xffffffffu, acc.x, 8);
    acc.y += __shfl_down_sync(0xffffffffu, acc.y, 8);
    acc.z += __shfl_down_sync(0xffffffffu, acc.z, 8);
    acc.w += __shfl_down_sync(0xffffffffu, acc.w, 8);
    acc.x += __shfl_down_sync(0xffffffffu, acc.x, 16);
    acc.y += __shfl_down_sync(0xffffffffu, acc.y, 16);
    acc.z += __shfl_down_sync(0xffffffffu, acc.z, 16);
    acc.w += __shfl_down_sync(0xffffffffu, acc.w, 16);

    if (lane < 8) {
        // undo column permutation: half2 idx p2 -> channel (p2&3)*8 + (p2>>2)*2
        int co0 = ((2 * c)     & 3) * 8 + ((2 * c)     >> 2) * 2;
        int co1 = ((2 * c + 1) & 3) * 8 + ((2 * c + 1) >> 2) * 2;
        *reinterpret_cast<float2*>(out + (size_t)m * C + co0) = make_float2(acc.x, acc.y);
        *reinterpret_cast<float2*>(out + (size_t)m * C + co1) = make_float2(acc.z, acc.w);
        sm[w][co0] = acc.x; sm[w][co0 + 1] = acc.y;
        sm[w][co1] = acc.z; sm[w][co1 + 1] = acc.w;
    }
    __syncthreads();
    if (tid < 32) {                      // deterministic per-CTA BN partials
        float s = 0.f, q = 0.f;
#pragma unroll
        for (int r = 0; r < 16; ++r) {
            float v = sm[r][tid];
            s += v; q += v * v;
        }
        g_part[blockIdx.x * 64 + tid]      = s;
        g_part[blockIdx.x * 64 + 32 + tid] = q;
    }
}

// -------- 4. BN partial reduction: 8192 -> 64 --------
__global__ __launch_bounds__(256) void k_bnmid() {
    __shared__ float ss[8][32], sq[8][32];
    int ch = threadIdx.x & 31, w = threadIdx.x >> 5;
    float s = 0.f, q = 0.f;
    for (int p = blockIdx.x * 128 + w; p < (blockIdx.x + 1) * 128; p += 8) {
        s += g_part[p * 64 + ch];
        q += g_part[p * 64 + 32 + ch];
    }
    ss[w][ch] = s; sq[w][ch] = q;
    __syncthreads();
    if (w == 0) {
        float S = 0.f, Q = 0.f;
#pragma unroll
        for (int t = 0; t < 8; ++t) { S += ss[t][ch]; Q += sq[t][ch]; }
        g_part2[blockIdx.x * 64 + ch]      = S;
        g_part2[blockIdx.x * 64 + 32 + ch] = Q;
    }
}

// -------- 5. BN finalize: 64 partials -> fused scale/shift --------
__global__ __launch_bounds__(256) void k_bnfinal(const float* __restrict__ gamma,
                                                 const float* __restrict__ beta) {
    __shared__ float ss[8][32], sq[8][32];
    int ch = threadIdx.x & 31, w = threadIdx.x >> 5;
    float S = 0.f, Q = 0.f;
    for (int b = w; b < 64; b += 8) {
        S += g_part2[b * 64 + ch];
        Q += g_part2[b * 64 + 32 + ch];
    }
    ss[w][ch] = S; sq[w][ch] = Q;
    __syncthreads();
    if (w == 0) {
        float St = 0.f, Qt = 0.f;
#pragma unroll
        for (int t = 0; t < 8; ++t) { St += ss[t][ch]; Qt += sq[t][ch]; }
        float mean  = St * (1.0f / NN);
        float var   = Qt * (1.0f / NN) - mean * mean;
        float rstd  = rsqrtf(var + EPS_F);
        float scale = gamma[ch] * rstd;
        g_stats[ch]      = scale;
        g_stats[32 + ch] = beta[ch] - mean * scale;
    }
}

// -------- 6. apply BN + ReLU --------
__global__ __launch_bounds__(256) void k_apply(float* __restrict__ out) {
    int i = blockIdx.x * blockDim.x + threadIdx.x;
    if (i >= NN * C) return;
    int   ch = i & 31;
    float y  = fmaf(out[i], g_stats[ch], g_stats[32 + ch]);
    out[i] = fmaxf(y, 0.f);
}

extern "C" void kernel_launch(void* const* d_in, const int* in_sizes, int n_in,
                              void* d_out, int out_size) {
    const float* data   = (const float*)d_in[0];
    const float* weight = (const float*)d_in[1];
    const float* gamma  = (const float*)d_in[2];
    const float* beta   = (const float*)d_in[3];
    const int*   neigh  = (const int*)d_in[4];
    float*       out    = (float*)d_out;

    k_init<<<NN / 256, 256>>>(weight);
    k_work<<<GEMM_BLKS + FILL_BLKS, 256>>>(data, neigh);
    k_gather<<<GB, 512>>>(out);
    k_bnmid<<<64, 256>>>();
    k_bnfinal<<<1, 256>>>(gamma, beta);
    k_apply<<<(NN * C + 255) / 256, 256>>>(out);
}